// round 4
// baseline (speedup 1.0000x reference)
#include <cuda_runtime.h>

// SSIM loss, fused single kernel. Separable 11-tap Gaussian, f32x2-packed math.
// img1, img2: [16,3,512,512] fp32. Output: scalar mean of SSIM map.

typedef unsigned long long u64;

constexpr int IMG_H = 512;
constexpr int IMG_W = 512;
constexpr int NPLANES = 48;              // 16 * 3
constexpr int TILE_W = 64;
constexpr int TILE_H = 32;
constexpr int HALO = 5;
constexpr int IN_W = TILE_W + 2 * HALO;  // 74
constexpr int IN_H = TILE_H + 2 * HALO;  // 42
constexpr int IMG_STRIDE = 76;           // padded row stride for input tiles
constexpr int H_STRIDE = 64;             // row stride for H-conv maps
constexpr int MAPSZ = IN_H * H_STRIDE;   // 2688
constexpr int NTHREADS = 512;
constexpr int GRID_X = IMG_W / TILE_W;   // 8
constexpr int GRID_Y = IMG_H / TILE_H;   // 16
constexpr int NBLOCKS = GRID_X * GRID_Y * NPLANES;  // 6144
constexpr int SMEM_FLOATS = 2 * IN_H * IMG_STRIDE + 5 * MAPSZ;  // ~79KB
constexpr float C1f = 0.0001f;
constexpr float C2f = 0.0009f;

// Gaussian(sigma=1.5) 1D weights as f32x2 (same value in both lanes).
// lane value bit patterns: see scalar table below.
__constant__ u64 G2[11] = {
    0x3A86CAB53A86CAB5ull,  // 0.00102838
    0x3BF8FF053BF8FF05ull,  // 0.00759876
    0x3D13758B3D13758Bull,  // 0.03600077
    0x3DDFF87F3DDFF87Full,  // 0.10936069
    0x3E5A1DE03E5A1DE0ull,  // 0.21300459
    0x3E8832B03E8832B0ull,  // 0.26601172
    0x3E5A1DE03E5A1DE0ull,
    0x3DDFF87F3DDFF87Full,
    0x3D13758B3D13758Bull,
    0x3BF8FF053BF8FF05ull,
    0x3A86CAB53A86CAB5ull
};

__device__ float g_partial[NBLOCKS];
__device__ unsigned int g_count;   // starts 0 (BSS), self-resets each call

// ---- f32x2 helpers ----
__device__ __forceinline__ u64 fma2(u64 a, u64 b, u64 c) {
    u64 d;
    asm("fma.rn.f32x2 %0, %1, %2, %3;" : "=l"(d) : "l"(a), "l"(b), "l"(c));
    return d;
}
__device__ __forceinline__ u64 mul2(u64 a, u64 b) {
    u64 d;
    asm("mul.rn.f32x2 %0, %1, %2;" : "=l"(d) : "l"(a), "l"(b));
    return d;
}
__device__ __forceinline__ u64 pack2(float lo, float hi) {
    u64 d;
    asm("mov.b64 %0, {%1, %2};" : "=l"(d) : "f"(lo), "f"(hi));
    return d;
}
__device__ __forceinline__ void unpack2(u64 v, float& lo, float& hi) {
    asm("mov.b64 {%0, %1}, %2;" : "=f"(lo), "=f"(hi) : "l"(v));
}

// 11-tap conv of a 12-entry packed window -> 2 packed outputs (cols cw, cw+1)
__device__ __forceinline__ void conv_pair(const u64* __restrict__ pw, u64& A, u64& B) {
    u64 a = 0ull, b = 0ull;
#pragma unroll
    for (int j = 0; j < 11; j++) {
        u64 g = G2[j];
        a = fma2(g, pw[j], a);
        b = fma2(g, pw[j + 1], b);
    }
    A = a; B = b;
}

// Load rows (r, r+1), cols cw..cw+11 of s, packed over rows.
__device__ __forceinline__ void load_pw(const float* __restrict__ s, int r, int cw,
                                        u64* __restrict__ pw) {
    const float* r0 = s + r * IMG_STRIDE + cw;
    const float* r1 = r0 + IMG_STRIDE;
#pragma unroll
    for (int i = 0; i < 6; i++) {
        float2 a = *reinterpret_cast<const float2*>(r0 + 2 * i);
        float2 b = *reinterpret_cast<const float2*>(r1 + 2 * i);
        pw[2 * i]     = pack2(a.x, b.x);
        pw[2 * i + 1] = pack2(a.y, b.y);
    }
}

// Same but elementwise product of two sources (for the xy map); low liveness.
__device__ __forceinline__ void load_pw_prod(const float* __restrict__ sa,
                                             const float* __restrict__ sb,
                                             int r, int cw, u64* __restrict__ pw) {
    const float* a0 = sa + r * IMG_STRIDE + cw;
    const float* a1 = a0 + IMG_STRIDE;
    const float* b0 = sb + r * IMG_STRIDE + cw;
    const float* b1 = b0 + IMG_STRIDE;
#pragma unroll
    for (int i = 0; i < 6; i++) {
        float2 xa = *reinterpret_cast<const float2*>(a0 + 2 * i);
        float2 ya = *reinterpret_cast<const float2*>(a1 + 2 * i);
        float2 xb = *reinterpret_cast<const float2*>(b0 + 2 * i);
        float2 yb = *reinterpret_cast<const float2*>(b1 + 2 * i);
        pw[2 * i]     = mul2(pack2(xa.x, ya.x), pack2(xb.x, yb.x));
        pw[2 * i + 1] = mul2(pack2(xa.y, ya.y), pack2(xb.y, yb.y));
    }
}

// Store packed pair results (A=col cw rows r/r+1, B=col cw+1 rows r/r+1).
__device__ __forceinline__ void store_pair(float* __restrict__ map, int r, int cw,
                                           u64 A, u64 B) {
    float ar, ar1, br, br1;
    unpack2(A, ar, ar1);
    unpack2(B, br, br1);
    *reinterpret_cast<float2*>(map + r * H_STRIDE + cw)       = make_float2(ar, br);
    *reinterpret_cast<float2*>(map + (r + 1) * H_STRIDE + cw) = make_float2(ar1, br1);
}

__device__ __forceinline__ float ssim_px(float mu1, float mu2, float x2, float y2, float xy) {
    float mu11 = mu1 * mu1, mu22 = mu2 * mu2, mu12 = mu1 * mu2;
    float num = (2.f * mu12 + C1f) * (2.f * (xy - mu12) + C2f);
    float den = (mu11 + mu22 + C1f) * ((x2 - mu11) + (y2 - mu22) + C2f);
    return num / den;
}

__global__ void __launch_bounds__(NTHREADS, 2)
ssim_main_kernel(const float* __restrict__ img1, const float* __restrict__ img2,
                 float* __restrict__ out) {
    extern __shared__ float sm[];
    float* s1 = sm;                           // [IN_H][IMG_STRIDE]
    float* s2 = sm + IN_H * IMG_STRIDE;
    float* sH = sm + 2 * IN_H * IMG_STRIDE;   // [5][IN_H][H_STRIDE]: mu1,mu2,x2,y2,xy

    const int tid = threadIdx.x;
    const int plane = blockIdx.z;
    const int ty = blockIdx.y * TILE_H;
    const int tx = blockIdx.x * TILE_W;
    const float* p1 = img1 + (size_t)plane * IMG_H * IMG_W;
    const float* p2 = img2 + (size_t)plane * IMG_H * IMG_W;

    // ---- Phase 1: load input tiles (zero halo at image edges) ----
    for (int i = tid; i < IN_H * IN_W; i += NTHREADS) {
        int r = i / IN_W, c = i - r * IN_W;
        int gy = ty + r - HALO, gx = tx + c - HALO;
        float v1 = 0.f, v2 = 0.f;
        if (((unsigned)gy < (unsigned)IMG_H) & ((unsigned)gx < (unsigned)IMG_W)) {
            int gi = gy * IMG_W + gx;
            v1 = __ldg(p1 + gi);
            v2 = __ldg(p2 + gi);
        }
        s1[r * IMG_STRIDE + c] = v1;
        s2[r * IMG_STRIDE + c] = v2;
    }
    __syncthreads();

    // ---- Phase 2: horizontal conv of 5 maps, f32x2 packed over row pairs.
    // Warp-task = (row-pair 0..20, group 0..2); thread = column pair (2*lane).
    {
        const int wid = tid >> 5;
        const int lane = tid & 31;
        const int cw = 2 * lane;
        for (int task = wid; task < 63; task += NTHREADS / 32) {
            int g = task / 21;
            int pr = task - g * 21;
            int r = 2 * pr;
            u64 pw[12], A, B;
            if (g == 0) {
                load_pw(s1, r, cw, pw);
                conv_pair(pw, A, B);
                store_pair(sH + 0 * MAPSZ, r, cw, A, B);          // mu1
#pragma unroll
                for (int i = 0; i < 12; i++) pw[i] = mul2(pw[i], pw[i]);
                conv_pair(pw, A, B);
                store_pair(sH + 2 * MAPSZ, r, cw, A, B);          // x^2
            } else if (g == 1) {
                load_pw(s2, r, cw, pw);
                conv_pair(pw, A, B);
                store_pair(sH + 1 * MAPSZ, r, cw, A, B);          // mu2
#pragma unroll
                for (int i = 0; i < 12; i++) pw[i] = mul2(pw[i], pw[i]);
                conv_pair(pw, A, B);
                store_pair(sH + 3 * MAPSZ, r, cw, A, B);          // y^2
            } else {
                load_pw_prod(s1, s2, r, cw, pw);
                conv_pair(pw, A, B);
                store_pair(sH + 4 * MAPSZ, r, cw, A, B);          // x*y
            }
        }
    }
    __syncthreads();

    // ---- Phase 3: vertical conv, f32x2 packed over column pairs.
    // Thread = (col-pair = tid&31, 2-row strip = (tid>>5)*2). Exactly 512 tasks.
    float lsum = 0.f;
    {
        const int cp = tid & 31;               // cols 2cp, 2cp+1
        const int r0 = (tid >> 5) * 2;         // output rows r0, r0+1
        u64 acc[10];
#pragma unroll
        for (int m = 0; m < 5; m++) {
            const u64* col = reinterpret_cast<const u64*>(sH + m * MAPSZ + r0 * H_STRIDE) + cp;
            u64 w[12];
#pragma unroll
            for (int i = 0; i < 12; i++) w[i] = col[i * (H_STRIDE / 2)];
            u64 a = 0ull, b = 0ull;
#pragma unroll
            for (int j = 0; j < 11; j++) {
                u64 g = G2[j];
                a = fma2(g, w[j], a);
                b = fma2(g, w[j + 1], b);
            }
            acc[2 * m] = a;                    // row r0 (packed cols)
            acc[2 * m + 1] = b;                // row r0+1
        }
#pragma unroll
        for (int rr = 0; rr < 2; rr++) {
            float m1l, m1h, m2l, m2h, x2l, x2h, y2l, y2h, xyl, xyh;
            unpack2(acc[0 + rr], m1l, m1h);
            unpack2(acc[2 + rr], m2l, m2h);
            unpack2(acc[4 + rr], x2l, x2h);
            unpack2(acc[6 + rr], y2l, y2h);
            unpack2(acc[8 + rr], xyl, xyh);
            lsum += ssim_px(m1l, m2l, x2l, y2l, xyl);
            lsum += ssim_px(m1h, m2h, x2h, y2h, xyh);
        }
    }

    // ---- Block reduce (fp32) ----
    __shared__ float wsum[NTHREADS / 32];
#pragma unroll
    for (int o = 16; o > 0; o >>= 1) lsum += __shfl_xor_sync(0xFFFFFFFFu, lsum, o);
    if ((tid & 31) == 0) wsum[tid >> 5] = lsum;
    __syncthreads();

    const int bid = (blockIdx.z * GRID_Y + blockIdx.y) * GRID_X + blockIdx.x;
    __shared__ bool isLast;
    if (tid == 0) {
        float s = 0.f;
#pragma unroll
        for (int i = 0; i < NTHREADS / 32; i++) s += wsum[i];
        g_partial[bid] = s;
        __threadfence();
        unsigned int old = atomicAdd(&g_count, 1u);
        isLast = (old == (unsigned)(NBLOCKS - 1));
    }
    __syncthreads();

    // ---- Last block: final reduction in double ----
    if (isLast) {
        double d = 0.0;
#pragma unroll
        for (int k = 0; k < NBLOCKS / NTHREADS; k++)
            d += (double)g_partial[tid + k * NTHREADS];
#pragma unroll
        for (int o = 16; o > 0; o >>= 1) d += __shfl_xor_sync(0xFFFFFFFFu, d, o);
        __shared__ double dsum[NTHREADS / 32];
        if ((tid & 31) == 0) dsum[tid >> 5] = d;
        __syncthreads();
        if (tid == 0) {
            double s = 0.0;
#pragma unroll
            for (int i = 0; i < NTHREADS / 32; i++) s += dsum[i];
            out[0] = (float)(s / (double)((size_t)NPLANES * IMG_H * IMG_W));
            g_count = 0;   // self-reset for next graph replay
        }
    }
}

extern "C" void kernel_launch(void* const* d_in, const int* in_sizes, int n_in,
                              void* d_out, int out_size) {
    const float* img1 = (const float*)d_in[0];
    const float* img2 = (const float*)d_in[1];
    float* out = (float*)d_out;

    cudaFuncSetAttribute(ssim_main_kernel,
                         cudaFuncAttributeMaxDynamicSharedMemorySize,
                         SMEM_FLOATS * (int)sizeof(float));

    dim3 grid(GRID_X, GRID_Y, NPLANES);
    ssim_main_kernel<<<grid, NTHREADS, SMEM_FLOATS * sizeof(float)>>>(img1, img2, out);
}

// round 5
// speedup vs baseline: 1.4951x; 1.4951x over previous
#include <cuda_runtime.h>

// SSIM loss, fused single kernel (separable 11-tap Gaussian).
// img1, img2: [16,3,512,512] fp32. Output: scalar mean of SSIM map.
// R5: 32x32 tiles, 256 threads, 5 CTAs/SM for latency overlap.

constexpr int IMG_H = 512;
constexpr int IMG_W = 512;
constexpr int NPLANES = 48;              // 16 * 3
constexpr int TILE_W = 32;
constexpr int TILE_H = 32;
constexpr int HALO = 5;
constexpr int IN_W = TILE_W + 2 * HALO;  // 42
constexpr int IN_H = TILE_H + 2 * HALO;  // 42
constexpr int IMG_STRIDE = 44;           // padded row stride (44*4B = 176 = 11*16, float4-aligned)
constexpr int H_STRIDE = 32;             // row stride for H-conv maps
constexpr int MAPSZ = IN_H * H_STRIDE;   // 1344
constexpr int NTHREADS = 256;
constexpr int GRID_X = IMG_W / TILE_W;   // 16
constexpr int GRID_Y = IMG_H / TILE_H;   // 16
constexpr int NBLOCKS = GRID_X * GRID_Y * NPLANES;  // 12288
constexpr int NT2 = IN_H * (TILE_W / 8); // 168 row-octets
constexpr int SMEM_FLOATS = 2 * IN_H * IMG_STRIDE + 5 * MAPSZ;  // 10416 (~41.7KB)
constexpr float C1f = 0.0001f;
constexpr float C2f = 0.0009f;

// Gaussian(sigma=1.5) 1D weights, normalized (w2d = outer(g,g))
__device__ constexpr float G[11] = {
    0.00102838f, 0.00759876f, 0.03600077f, 0.10936070f, 0.21300460f,
    0.26601170f,
    0.21300460f, 0.10936070f, 0.03600077f, 0.00759876f, 0.00102838f
};

__device__ float g_partial[NBLOCKS];
__device__ unsigned int g_count;   // starts 0 (BSS), self-resets each call

// 11-tap horizontal conv of an 18-float window -> 8 outputs (weights fold to FFMA-imm)
__device__ __forceinline__ void conv_row8(const float* __restrict__ w, float* __restrict__ acc) {
#pragma unroll
    for (int k = 0; k < 8; k++) {
        float s = 0.f;
#pragma unroll
        for (int j = 0; j < 11; j++) s = fmaf(G[j], w[k + j], s);
        acc[k] = s;
    }
}

__device__ __forceinline__ void load20(const float* __restrict__ src, float* __restrict__ w) {
    const float4* s4 = reinterpret_cast<const float4*>(src);
#pragma unroll
    for (int i = 0; i < 5; i++) {
        float4 v = s4[i];
        w[4 * i + 0] = v.x; w[4 * i + 1] = v.y; w[4 * i + 2] = v.z; w[4 * i + 3] = v.w;
    }
}

__device__ __forceinline__ void store8(float* __restrict__ p, const float* __restrict__ acc) {
    float4* q = reinterpret_cast<float4*>(p);
    q[0] = make_float4(acc[0], acc[1], acc[2], acc[3]);
    q[1] = make_float4(acc[4], acc[5], acc[6], acc[7]);
}

__global__ void __launch_bounds__(NTHREADS, 5)
ssim_main_kernel(const float* __restrict__ img1, const float* __restrict__ img2,
                 float* __restrict__ out) {
    extern __shared__ float sm[];
    float* s1 = sm;                           // [IN_H][IMG_STRIDE]
    float* s2 = sm + IN_H * IMG_STRIDE;
    float* sH = sm + 2 * IN_H * IMG_STRIDE;   // [5][IN_H][H_STRIDE]: mu1,mu2,x2,y2,xy

    const int tid = threadIdx.x;
    const int plane = blockIdx.z;
    const int ty = blockIdx.y * TILE_H;
    const int tx = blockIdx.x * TILE_W;
    const float* p1 = img1 + (size_t)plane * IMG_H * IMG_W;
    const float* p2 = img2 + (size_t)plane * IMG_H * IMG_W;

    // ---- Phase 1: load input tiles (zero halo at image edges) ----
    for (int i = tid; i < IN_H * IN_W; i += NTHREADS) {
        int r = i / IN_W, c = i - r * IN_W;
        int gy = ty + r - HALO, gx = tx + c - HALO;
        float v1 = 0.f, v2 = 0.f;
        if (((unsigned)gy < (unsigned)IMG_H) & ((unsigned)gx < (unsigned)IMG_W)) {
            int gi = gy * IMG_W + gx;
            v1 = __ldg(p1 + gi);
            v2 = __ldg(p2 + gi);
        }
        s1[r * IMG_STRIDE + c] = v1;
        s2[r * IMG_STRIDE + c] = v2;
    }
    __syncthreads();

    // ---- Phase 2: horizontal conv of 5 maps.
    // Task = (row-octet, group). group 0: mu1+x2; group 1: mu2+y2; group 2: xy.
    // 504 tasks / 256 threads.
    for (int t = tid; t < NT2 * 3; t += NTHREADS) {
        int ro = t % NT2;
        int g = t / NT2;
        int r = ro >> 2;                      // 4 octets per row
        int c0 = (ro & 3) << 3;
        float* hrow = sH + r * H_STRIDE + c0;
        float acc[8];
        if (g == 0) {
            float w[20];
            load20(s1 + r * IMG_STRIDE + c0, w);
            conv_row8(w, acc);
            store8(hrow + 0 * MAPSZ, acc);            // mu1
#pragma unroll
            for (int i = 0; i < 18; i++) w[i] = w[i] * w[i];
            conv_row8(w, acc);
            store8(hrow + 2 * MAPSZ, acc);            // x^2
        } else if (g == 1) {
            float w[20];
            load20(s2 + r * IMG_STRIDE + c0, w);
            conv_row8(w, acc);
            store8(hrow + 1 * MAPSZ, acc);            // mu2
#pragma unroll
            for (int i = 0; i < 18; i++) w[i] = w[i] * w[i];
            conv_row8(w, acc);
            store8(hrow + 3 * MAPSZ, acc);            // y^2
        } else {
            float wa[20], wb[20];
            load20(s1 + r * IMG_STRIDE + c0, wa);
            load20(s2 + r * IMG_STRIDE + c0, wb);
#pragma unroll
            for (int i = 0; i < 18; i++) wa[i] = wa[i] * wb[i];
            conv_row8(wa, acc);
            store8(hrow + 4 * MAPSZ, acc);            // x*y
        }
    }
    __syncthreads();

    // ---- Phase 3: vertical conv (4-row strip per thread, exactly 256 tasks) ----
    float lsum = 0.f;
    {
        const int c = tid & 31;
        const int r0 = (tid >> 5) * 4;                // 8 strips of 4 rows
        float am1[4], am2[4], ax2[4], ay2[4], axy[4];
#pragma unroll
        for (int k = 0; k < 4; k++) { am1[k] = 0.f; am2[k] = 0.f; ax2[k] = 0.f; ay2[k] = 0.f; axy[k] = 0.f; }
        const float* h0 = sH + 0 * MAPSZ + r0 * H_STRIDE + c;
        const float* h1 = sH + 1 * MAPSZ + r0 * H_STRIDE + c;
        const float* h2 = sH + 2 * MAPSZ + r0 * H_STRIDE + c;
        const float* h3 = sH + 3 * MAPSZ + r0 * H_STRIDE + c;
        const float* h4 = sH + 4 * MAPSZ + r0 * H_STRIDE + c;
#pragma unroll
        for (int i = 0; i < 14; i++) {
            float v0 = h0[i * H_STRIDE];
            float v1 = h1[i * H_STRIDE];
            float v2 = h2[i * H_STRIDE];
            float v3 = h3[i * H_STRIDE];
            float v4 = h4[i * H_STRIDE];
#pragma unroll
            for (int ro = 0; ro < 4; ro++) {
                const int j = i - ro;
                if (j >= 0 && j < 11) {
                    am1[ro] = fmaf(G[j], v0, am1[ro]);
                    am2[ro] = fmaf(G[j], v1, am2[ro]);
                    ax2[ro] = fmaf(G[j], v2, ax2[ro]);
                    ay2[ro] = fmaf(G[j], v3, ay2[ro]);
                    axy[ro] = fmaf(G[j], v4, axy[ro]);
                }
            }
        }
#pragma unroll
        for (int ro = 0; ro < 4; ro++) {
            float mu1 = am1[ro], mu2 = am2[ro];
            float mu11 = mu1 * mu1, mu22 = mu2 * mu2, mu12 = mu1 * mu2;
            float sx = ax2[ro] - mu11;
            float sy = ay2[ro] - mu22;
            float sxy = axy[ro] - mu12;
            float num = (2.f * mu12 + C1f) * (2.f * sxy + C2f);
            float den = (mu11 + mu22 + C1f) * (sx + sy + C2f);
            lsum += num / den;
        }
    }

    // ---- Block reduce (fp32) ----
    __shared__ float wsum[NTHREADS / 32];
#pragma unroll
    for (int o = 16; o > 0; o >>= 1) lsum += __shfl_xor_sync(0xFFFFFFFFu, lsum, o);
    if ((tid & 31) == 0) wsum[tid >> 5] = lsum;
    __syncthreads();

    const int bid = (blockIdx.z * GRID_Y + blockIdx.y) * GRID_X + blockIdx.x;
    __shared__ bool isLast;
    if (tid == 0) {
        float s = 0.f;
#pragma unroll
        for (int i = 0; i < NTHREADS / 32; i++) s += wsum[i];
        g_partial[bid] = s;
        __threadfence();
        unsigned int old = atomicAdd(&g_count, 1u);
        isLast = (old == (unsigned)(NBLOCKS - 1));
    }
    __syncthreads();

    // ---- Last block: final reduction in double ----
    if (isLast) {
        double d = 0.0;
        for (int k = 0; k < NBLOCKS / NTHREADS; k++)
            d += (double)g_partial[tid + k * NTHREADS];
#pragma unroll
        for (int o = 16; o > 0; o >>= 1) d += __shfl_xor_sync(0xFFFFFFFFu, d, o);
        __shared__ double dsum[NTHREADS / 32];
        if ((tid & 31) == 0) dsum[tid >> 5] = d;
        __syncthreads();
        if (tid == 0) {
            double s = 0.0;
#pragma unroll
            for (int i = 0; i < NTHREADS / 32; i++) s += dsum[i];
            out[0] = (float)(s / (double)((size_t)NPLANES * IMG_H * IMG_W));
            g_count = 0;   // self-reset for next graph replay
        }
    }
}

extern "C" void kernel_launch(void* const* d_in, const int* in_sizes, int n_in,
                              void* d_out, int out_size) {
    const float* img1 = (const float*)d_in[0];
    const float* img2 = (const float*)d_in[1];
    float* out = (float*)d_out;

    cudaFuncSetAttribute(ssim_main_kernel,
                         cudaFuncAttributeMaxDynamicSharedMemorySize,
                         SMEM_FLOATS * (int)sizeof(float));

    dim3 grid(GRID_X, GRID_Y, NPLANES);
    ssim_main_kernel<<<grid, NTHREADS, SMEM_FLOATS * sizeof(float)>>>(img1, img2, out);
}

// round 6
// speedup vs baseline: 1.8131x; 1.2127x over previous
#include <cuda_runtime.h>

// SSIM loss, fused single kernel (separable 11-tap Gaussian).
// img1, img2: [16,3,512,512] fp32. Output: scalar mean of SSIM map.
// R6: R5 (32x32 tiles, 256 thr, 5 CTAs/SM) + ALU-slot cuts (2D phase-1 map,
//     fast divide, hoisted address math).

constexpr int IMG_H = 512;
constexpr int IMG_W = 512;
constexpr int NPLANES = 48;              // 16 * 3
constexpr int TILE_W = 32;
constexpr int TILE_H = 32;
constexpr int HALO = 5;
constexpr int IN_W = TILE_W + 2 * HALO;  // 42
constexpr int IN_H = TILE_H + 2 * HALO;  // 42
constexpr int IMG_STRIDE = 44;           // padded row stride, float4-friendly
constexpr int H_STRIDE = 32;             // row stride for H-conv maps
constexpr int MAPSZ = IN_H * H_STRIDE;   // 1344
constexpr int NTHREADS = 256;
constexpr int GRID_X = IMG_W / TILE_W;   // 16
constexpr int GRID_Y = IMG_H / TILE_H;   // 16
constexpr int NBLOCKS = GRID_X * GRID_Y * NPLANES;  // 12288
constexpr int NT2 = IN_H * (TILE_W / 8); // 168 row-octets
constexpr int SMEM_FLOATS = 2 * IN_H * IMG_STRIDE + 5 * MAPSZ;  // 10416 (~41.7KB)
constexpr float C1f = 0.0001f;
constexpr float C2f = 0.0009f;

// Gaussian(sigma=1.5) 1D weights, normalized (w2d = outer(g,g))
__device__ constexpr float G[11] = {
    0.00102838f, 0.00759876f, 0.03600077f, 0.10936070f, 0.21300460f,
    0.26601170f,
    0.21300460f, 0.10936070f, 0.03600077f, 0.00759876f, 0.00102838f
};

__device__ float g_partial[NBLOCKS];
__device__ unsigned int g_count;   // starts 0 (BSS), self-resets each call

// 11-tap horizontal conv of an 18-float window -> 8 outputs (weights fold to FFMA-imm)
__device__ __forceinline__ void conv_row8(const float* __restrict__ w, float* __restrict__ acc) {
#pragma unroll
    for (int k = 0; k < 8; k++) {
        float s = 0.f;
#pragma unroll
        for (int j = 0; j < 11; j++) s = fmaf(G[j], w[k + j], s);
        acc[k] = s;
    }
}

__device__ __forceinline__ void load20(const float* __restrict__ src, float* __restrict__ w) {
    const float4* s4 = reinterpret_cast<const float4*>(src);
#pragma unroll
    for (int i = 0; i < 5; i++) {
        float4 v = s4[i];
        w[4 * i + 0] = v.x; w[4 * i + 1] = v.y; w[4 * i + 2] = v.z; w[4 * i + 3] = v.w;
    }
}

__device__ __forceinline__ void store8(float* __restrict__ p, const float* __restrict__ acc) {
    float4* q = reinterpret_cast<float4*>(p);
    q[0] = make_float4(acc[0], acc[1], acc[2], acc[3]);
    q[1] = make_float4(acc[4], acc[5], acc[6], acc[7]);
}

__global__ void __launch_bounds__(NTHREADS, 5)
ssim_main_kernel(const float* __restrict__ img1, const float* __restrict__ img2,
                 float* __restrict__ out) {
    extern __shared__ float sm[];
    float* s1 = sm;                           // [IN_H][IMG_STRIDE]
    float* s2 = sm + IN_H * IMG_STRIDE;
    float* sH = sm + 2 * IN_H * IMG_STRIDE;   // [5][IN_H][H_STRIDE]: mu1,mu2,x2,y2,xy

    const int tid = threadIdx.x;
    const int plane = blockIdx.z;
    const int ty = blockIdx.y * TILE_H;
    const int tx = blockIdx.x * TILE_W;
    const float* p1 = img1 + (size_t)plane * IMG_H * IMG_W;
    const float* p2 = img2 + (size_t)plane * IMG_H * IMG_W;

    // ---- Phase 1: load input tiles (zero halo at image edges) ----
    // 252 threads: thread = (r0 = tid/42, c = tid%42); rows r0 + 6k, k=0..6.
    if (tid < 252) {
        const int r0 = tid / IN_W;           // single div, strength-reduced
        const int c = tid - r0 * IN_W;
        const int gx = tx + c - HALO;
        const bool cin = (unsigned)gx < (unsigned)IMG_W;
        const float* c1 = p1 + gx;
        const float* c2 = p2 + gx;
        float* d1 = s1 + r0 * IMG_STRIDE + c;
        float* d2 = s2 + r0 * IMG_STRIDE + c;
#pragma unroll
        for (int k = 0; k < 7; k++) {
            const int gy = ty + r0 + 6 * k - HALO;
            float v1 = 0.f, v2 = 0.f;
            if (cin & ((unsigned)gy < (unsigned)IMG_H)) {
                v1 = __ldg(c1 + gy * IMG_W);
                v2 = __ldg(c2 + gy * IMG_W);
            }
            d1[6 * k * IMG_STRIDE] = v1;
            d2[6 * k * IMG_STRIDE] = v2;
        }
    }
    __syncthreads();

    // ---- Phase 2: horizontal conv of 5 maps.
    // Task = (row-octet, group). group 0: mu1+x2; group 1: mu2+y2; group 2: xy.
    // 504 tasks / 256 threads.
    for (int t = tid; t < NT2 * 3; t += NTHREADS) {
        int ro = t % NT2;
        int g = t / NT2;
        int r = ro >> 2;                      // 4 octets per row
        int c0 = (ro & 3) << 3;
        const float* src1 = s1 + r * IMG_STRIDE + c0;
        float* hrow = sH + r * H_STRIDE + c0;
        float acc[8];
        if (g == 0) {
            float w[20];
            load20(src1, w);
            conv_row8(w, acc);
            store8(hrow + 0 * MAPSZ, acc);            // mu1
#pragma unroll
            for (int i = 0; i < 18; i++) w[i] = w[i] * w[i];
            conv_row8(w, acc);
            store8(hrow + 2 * MAPSZ, acc);            // x^2
        } else if (g == 1) {
            float w[20];
            load20(src1 + IN_H * IMG_STRIDE, w);      // s2
            conv_row8(w, acc);
            store8(hrow + 1 * MAPSZ, acc);            // mu2
#pragma unroll
            for (int i = 0; i < 18; i++) w[i] = w[i] * w[i];
            conv_row8(w, acc);
            store8(hrow + 3 * MAPSZ, acc);            // y^2
        } else {
            float wa[20], wb[20];
            load20(src1, wa);
            load20(src1 + IN_H * IMG_STRIDE, wb);
#pragma unroll
            for (int i = 0; i < 18; i++) wa[i] = wa[i] * wb[i];
            conv_row8(wa, acc);
            store8(hrow + 4 * MAPSZ, acc);            // x*y
        }
    }
    __syncthreads();

    // ---- Phase 3: vertical conv (4-row strip per thread, exactly 256 tasks) ----
    float lsum = 0.f;
    {
        const int c = tid & 31;
        const int r0 = (tid >> 5) * 4;                // 8 strips of 4 rows
        float am1[4], am2[4], ax2[4], ay2[4], axy[4];
#pragma unroll
        for (int k = 0; k < 4; k++) { am1[k] = 0.f; am2[k] = 0.f; ax2[k] = 0.f; ay2[k] = 0.f; axy[k] = 0.f; }
        const float* h0 = sH + 0 * MAPSZ + r0 * H_STRIDE + c;
#pragma unroll
        for (int i = 0; i < 14; i++) {
            float v0 = h0[i * H_STRIDE + 0 * MAPSZ];
            float v1 = h0[i * H_STRIDE + 1 * MAPSZ];
            float v2 = h0[i * H_STRIDE + 2 * MAPSZ];
            float v3 = h0[i * H_STRIDE + 3 * MAPSZ];
            float v4 = h0[i * H_STRIDE + 4 * MAPSZ];
#pragma unroll
            for (int ro = 0; ro < 4; ro++) {
                const int j = i - ro;
                if (j >= 0 && j < 11) {               // compile-time resolved
                    am1[ro] = fmaf(G[j], v0, am1[ro]);
                    am2[ro] = fmaf(G[j], v1, am2[ro]);
                    ax2[ro] = fmaf(G[j], v2, ax2[ro]);
                    ay2[ro] = fmaf(G[j], v3, ay2[ro]);
                    axy[ro] = fmaf(G[j], v4, axy[ro]);
                }
            }
        }
#pragma unroll
        for (int ro = 0; ro < 4; ro++) {
            float mu1 = am1[ro], mu2 = am2[ro];
            float mu11 = mu1 * mu1, mu22 = mu2 * mu2, mu12 = mu1 * mu2;
            float sx = ax2[ro] - mu11;
            float sy = ay2[ro] - mu22;
            float sxy = axy[ro] - mu12;
            float num = (2.f * mu12 + C1f) * (2.f * sxy + C2f);
            float den = (mu11 + mu22 + C1f) * (sx + sy + C2f);
            lsum += __fdividef(num, den);
        }
    }

    // ---- Block reduce (fp32) ----
    __shared__ float wsum[NTHREADS / 32];
#pragma unroll
    for (int o = 16; o > 0; o >>= 1) lsum += __shfl_xor_sync(0xFFFFFFFFu, lsum, o);
    if ((tid & 31) == 0) wsum[tid >> 5] = lsum;
    __syncthreads();

    const int bid = (blockIdx.z * GRID_Y + blockIdx.y) * GRID_X + blockIdx.x;
    __shared__ bool isLast;
    if (tid == 0) {
        float s = 0.f;
#pragma unroll
        for (int i = 0; i < NTHREADS / 32; i++) s += wsum[i];
        g_partial[bid] = s;
        __threadfence();
        unsigned int old = atomicAdd(&g_count, 1u);
        isLast = (old == (unsigned)(NBLOCKS - 1));
    }
    __syncthreads();

    // ---- Last block: final reduction in double ----
    if (isLast) {
        double d = 0.0;
        for (int k = 0; k < NBLOCKS / NTHREADS; k++)
            d += (double)g_partial[tid + k * NTHREADS];
#pragma unroll
        for (int o = 16; o > 0; o >>= 1) d += __shfl_xor_sync(0xFFFFFFFFu, d, o);
        __shared__ double dsum[NTHREADS / 32];
        if ((tid & 31) == 0) dsum[tid >> 5] = d;
        __syncthreads();
        if (tid == 0) {
            double s = 0.0;
#pragma unroll
            for (int i = 0; i < NTHREADS / 32; i++) s += dsum[i];
            out[0] = (float)(s / (double)((size_t)NPLANES * IMG_H * IMG_W));
            g_count = 0;   // self-reset for next graph replay
        }
    }
}

extern "C" void kernel_launch(void* const* d_in, const int* in_sizes, int n_in,
                              void* d_out, int out_size) {
    const float* img1 = (const float*)d_in[0];
    const float* img2 = (const float*)d_in[1];
    float* out = (float*)d_out;

    cudaFuncSetAttribute(ssim_main_kernel,
                         cudaFuncAttributeMaxDynamicSharedMemorySize,
                         SMEM_FLOATS * (int)sizeof(float));

    dim3 grid(GRID_X, GRID_Y, NPLANES);
    ssim_main_kernel<<<grid, NTHREADS, SMEM_FLOATS * sizeof(float)>>>(img1, img2, out);
}

// round 7
// speedup vs baseline: 2.2967x; 1.2667x over previous
#include <cuda_runtime.h>

// SSIM loss, fused single kernel (separable 11-tap Gaussian).
// img1, img2: [16,3,512,512] fp32. Output: scalar mean of SSIM map.
// R7: u/d transform -> only 4 convolutions (cu, cd, cu2, cd2) instead of 5.
//     32x32 tiles, 256 thr, 5 CTAs/SM.

constexpr int IMG_H = 512;
constexpr int IMG_W = 512;
constexpr int NPLANES = 48;              // 16 * 3
constexpr int TILE_W = 32;
constexpr int TILE_H = 32;
constexpr int HALO = 5;
constexpr int IN_W = TILE_W + 2 * HALO;  // 42
constexpr int IN_H = TILE_H + 2 * HALO;  // 42
constexpr int IMG_STRIDE = 44;           // padded row stride, float4-friendly
constexpr int H_STRIDE = 32;             // row stride for H-conv maps
constexpr int MAPSZ = IN_H * H_STRIDE;   // 1344
constexpr int NTHREADS = 256;
constexpr int GRID_X = IMG_W / TILE_W;   // 16
constexpr int GRID_Y = IMG_H / TILE_H;   // 16
constexpr int NBLOCKS = GRID_X * GRID_Y * NPLANES;  // 12288
constexpr int NQUAD = IN_H * (TILE_W / 4);          // 336 row-quads
constexpr int NTASK2 = NQUAD * 2;                   // 672 phase-2 tasks
constexpr int SMEM_FLOATS = 2 * IN_H * IMG_STRIDE + 4 * MAPSZ;  // 9072 (~36.3KB)
constexpr float C1f = 0.0001f;
constexpr float C2f = 0.0009f;

// Gaussian(sigma=1.5) 1D weights, normalized (w2d = outer(g,g))
__device__ constexpr float G[11] = {
    0.00102838f, 0.00759876f, 0.03600077f, 0.10936070f, 0.21300460f,
    0.26601170f,
    0.21300460f, 0.10936070f, 0.03600077f, 0.00759876f, 0.00102838f
};

__device__ float g_partial[NBLOCKS];
__device__ unsigned int g_count;   // starts 0 (BSS), self-resets each call

// 11-tap horizontal conv of a 14-float window -> 4 outputs (weights fold to FFMA-imm)
__device__ __forceinline__ void conv_row4(const float* __restrict__ w, float* __restrict__ acc) {
#pragma unroll
    for (int k = 0; k < 4; k++) {
        float s = 0.f;
#pragma unroll
        for (int j = 0; j < 11; j++) s = fmaf(G[j], w[k + j], s);
        acc[k] = s;
    }
}

__device__ __forceinline__ void load16(const float* __restrict__ src, float* __restrict__ w) {
    const float4* s4 = reinterpret_cast<const float4*>(src);
#pragma unroll
    for (int i = 0; i < 4; i++) {
        float4 v = s4[i];
        w[4 * i + 0] = v.x; w[4 * i + 1] = v.y; w[4 * i + 2] = v.z; w[4 * i + 3] = v.w;
    }
}

__global__ void __launch_bounds__(NTHREADS, 5)
ssim_main_kernel(const float* __restrict__ img1, const float* __restrict__ img2,
                 float* __restrict__ out) {
    extern __shared__ float sm[];
    float* su = sm;                           // [IN_H][IMG_STRIDE]  u = x + y
    float* sd = sm + IN_H * IMG_STRIDE;       //                      d = x - y
    float* sH = sm + 2 * IN_H * IMG_STRIDE;   // [4][IN_H][H_STRIDE]: cu, cd, cu2, cd2

    const int tid = threadIdx.x;
    const int plane = blockIdx.z;
    const int ty = blockIdx.y * TILE_H;
    const int tx = blockIdx.x * TILE_W;
    const float* p1 = img1 + (size_t)plane * IMG_H * IMG_W;
    const float* p2 = img2 + (size_t)plane * IMG_H * IMG_W;

    // ---- Phase 1: load input tiles as u/d (zero halo at image edges) ----
    // 252 threads: thread = (r0 = tid/42, c = tid%42); rows r0 + 6k, k=0..6.
    if (tid < 252) {
        const int r0 = tid / IN_W;
        const int c = tid - r0 * IN_W;
        const int gx = tx + c - HALO;
        const bool cin = (unsigned)gx < (unsigned)IMG_W;
        const float* c1 = p1 + gx;
        const float* c2 = p2 + gx;
        float* du = su + r0 * IMG_STRIDE + c;
        float* dd = sd + r0 * IMG_STRIDE + c;
#pragma unroll
        for (int k = 0; k < 7; k++) {
            const int gy = ty + r0 + 6 * k - HALO;
            float v1 = 0.f, v2 = 0.f;
            if (cin & ((unsigned)gy < (unsigned)IMG_H)) {
                v1 = __ldg(c1 + gy * IMG_W);
                v2 = __ldg(c2 + gy * IMG_W);
            }
            du[6 * k * IMG_STRIDE] = v1 + v2;
            dd[6 * k * IMG_STRIDE] = v1 - v2;
        }
    }
    __syncthreads();

    // ---- Phase 2: horizontal conv of 4 maps.
    // Task = (row-quad, group). group 0: cu+cu2 from su; group 1: cd+cd2 from sd.
    // 672 tasks / 256 threads.
    for (int t = tid; t < NTASK2; t += NTHREADS) {
        int ro = t;
        int g = 0;
        if (ro >= NQUAD) { ro -= NQUAD; g = 1; }
        int r = ro >> 3;                      // 8 quads per row
        int c0 = (ro & 7) << 2;
        const float* src = (g == 0 ? su : sd) + r * IMG_STRIDE + c0;
        float* hrow = sH + (g == 0 ? 0 : 1) * MAPSZ + r * H_STRIDE + c0;
        float w[16], acc[4];
        load16(src, w);
        conv_row4(w, acc);                                    // cu or cd
        *reinterpret_cast<float4*>(hrow) = make_float4(acc[0], acc[1], acc[2], acc[3]);
#pragma unroll
        for (int i = 0; i < 14; i++) w[i] = w[i] * w[i];
        conv_row4(w, acc);                                    // cu2 or cd2
        *reinterpret_cast<float4*>(hrow + 2 * MAPSZ) =
            make_float4(acc[0], acc[1], acc[2], acc[3]);
    }
    __syncthreads();

    // ---- Phase 3: vertical conv (4-row strip per thread, exactly 256 tasks) ----
    float lsum = 0.f;
    {
        const int c = tid & 31;
        const int r0 = (tid >> 5) * 4;                // 8 strips of 4 rows
        float a0[4], a1[4], a2[4], a3[4];             // cu, cd, cu2, cd2
#pragma unroll
        for (int k = 0; k < 4; k++) { a0[k] = 0.f; a1[k] = 0.f; a2[k] = 0.f; a3[k] = 0.f; }
        const float* h0 = sH + r0 * H_STRIDE + c;
#pragma unroll
        for (int i = 0; i < 14; i++) {
            float v0 = h0[i * H_STRIDE + 0 * MAPSZ];
            float v1 = h0[i * H_STRIDE + 1 * MAPSZ];
            float v2 = h0[i * H_STRIDE + 2 * MAPSZ];
            float v3 = h0[i * H_STRIDE + 3 * MAPSZ];
#pragma unroll
            for (int ro = 0; ro < 4; ro++) {
                const int j = i - ro;
                if (j >= 0 && j < 11) {               // compile-time resolved
                    a0[ro] = fmaf(G[j], v0, a0[ro]);
                    a1[ro] = fmaf(G[j], v1, a1[ro]);
                    a2[ro] = fmaf(G[j], v2, a2[ro]);
                    a3[ro] = fmaf(G[j], v3, a3[ro]);
                }
            }
        }
#pragma unroll
        for (int ro = 0; ro < 4; ro++) {
            float cu = a0[ro], cd = a1[ro], cu2 = a2[ro], cd2 = a3[ro];
            float A = cu * cu;                        // (mu1+mu2)^2
            float B = cd * cd;                        // (mu1-mu2)^2
            float t1 = 0.5f * (A - B) + C1f;          // 2*mu1*mu2 + C1
            float t2 = 0.5f * ((cu2 - cd2) - (A - B)) + C2f;   // 2*sigma12 + C2
            float t3 = 0.5f * (A + B) + C1f;          // mu1^2+mu2^2 + C1
            float t4 = 0.5f * ((cu2 + cd2) - (A + B)) + C2f;   // sx+sy + C2
            lsum += __fdividef(t1 * t2, t3 * t4);
        }
    }

    // ---- Block reduce (fp32) ----
    __shared__ float wsum[NTHREADS / 32];
#pragma unroll
    for (int o = 16; o > 0; o >>= 1) lsum += __shfl_xor_sync(0xFFFFFFFFu, lsum, o);
    if ((tid & 31) == 0) wsum[tid >> 5] = lsum;
    __syncthreads();

    const int bid = (blockIdx.z * GRID_Y + blockIdx.y) * GRID_X + blockIdx.x;
    __shared__ bool isLast;
    if (tid == 0) {
        float s = 0.f;
#pragma unroll
        for (int i = 0; i < NTHREADS / 32; i++) s += wsum[i];
        g_partial[bid] = s;
        __threadfence();
        unsigned int old = atomicAdd(&g_count, 1u);
        isLast = (old == (unsigned)(NBLOCKS - 1));
    }
    __syncthreads();

    // ---- Last block: final reduction in double ----
    if (isLast) {
        double d = 0.0;
        for (int k = 0; k < NBLOCKS / NTHREADS; k++)
            d += (double)g_partial[tid + k * NTHREADS];
#pragma unroll
        for (int o = 16; o > 0; o >>= 1) d += __shfl_xor_sync(0xFFFFFFFFu, d, o);
        __shared__ double dsum[NTHREADS / 32];
        if ((tid & 31) == 0) dsum[tid >> 5] = d;
        __syncthreads();
        if (tid == 0) {
            double s = 0.0;
#pragma unroll
            for (int i = 0; i < NTHREADS / 32; i++) s += dsum[i];
            out[0] = (float)(s / (double)((size_t)NPLANES * IMG_H * IMG_W));
            g_count = 0;   // self-reset for next graph replay
        }
    }
}

extern "C" void kernel_launch(void* const* d_in, const int* in_sizes, int n_in,
                              void* d_out, int out_size) {
    const float* img1 = (const float*)d_in[0];
    const float* img2 = (const float*)d_in[1];
    float* out = (float*)d_out;

    cudaFuncSetAttribute(ssim_main_kernel,
                         cudaFuncAttributeMaxDynamicSharedMemorySize,
                         SMEM_FLOATS * (int)sizeof(float));

    dim3 grid(GRID_X, GRID_Y, NPLANES);
    ssim_main_kernel<<<grid, NTHREADS, SMEM_FLOATS * sizeof(float)>>>(img1, img2, out);
}